// round 9
// baseline (speedup 1.0000x reference)
#include <cuda_runtime.h>
#include <cuda_bf16.h>
#include <cstdint>

#define BATCH 8
#define SEQ   2048
#define CDIM  768
#define KD    768
#define MQ    (BATCH*SEQ)

typedef __nv_bfloat16 bf16;

// ---------------- scratch (device globals; allocation-free rule) -------------
__device__ bf16  g_qx[(size_t)MQ*CDIM];
__device__ bf16  g_kx[(size_t)MQ*CDIM];
__device__ bf16  g_w [(size_t)2*KD*CDIM];
__device__ bf16  g_q [(size_t)MQ*KD];
__device__ bf16  g_k [(size_t)MQ*KD];
__device__ bf16  g_vt[(size_t)BATCH*CDIM*SEQ];
__device__ float g_s [(size_t)BATCH*SEQ*SEQ];
__device__ bf16  g_dp[(size_t)BATCH*SEQ*SEQ];
__device__ float g_bias[(size_t)BATCH*CDIM];

// ---------------- helpers ----------------------------------------------------
__device__ __forceinline__ uint32_t smem_u32(const void* p) {
    uint32_t a;
    asm("{ .reg .u64 t; cvta.to.shared.u64 t, %1; cvt.u32.u64 %0, t; }" : "=r"(a) : "l"(p));
    return a;
}
__device__ __forceinline__ void cp16(uint32_t dst, const void* src) {
    asm volatile("cp.async.cg.shared.global [%0], [%1], 16;" :: "r"(dst), "l"(src));
}
__device__ __forceinline__ void cp_commit() {
    asm volatile("cp.async.commit_group;" ::: "memory");
}
template <int N>
__device__ __forceinline__ void cp_wait() {
    asm volatile("cp.async.wait_group %0;" :: "n"(N) : "memory");
}
__device__ __forceinline__ void ldsm4(uint32_t* r, uint32_t addr) {
    asm volatile("ldmatrix.sync.aligned.m8n8.x4.shared.b16 {%0,%1,%2,%3}, [%4];"
                 : "=r"(r[0]), "=r"(r[1]), "=r"(r[2]), "=r"(r[3]) : "r"(addr));
}
__device__ __forceinline__ void mma16816(float* c, const uint32_t* a, const uint32_t* b) {
    asm volatile(
        "mma.sync.aligned.m16n8k16.row.col.f32.bf16.bf16.f32 "
        "{%0,%1,%2,%3}, {%4,%5,%6,%7}, {%8,%9}, {%0,%1,%2,%3};"
        : "+f"(c[0]), "+f"(c[1]), "+f"(c[2]), "+f"(c[3])
        : "r"(a[0]), "r"(a[1]), "r"(a[2]), "r"(a[3]), "r"(b[0]), "r"(b[1]));
}

// ---------------- single-bf16 NT GEMM via mma.sync ---------------------------
// C[m,n] = sum_k A[m,k]*B[n,k]; A,B bf16, K-major, fp32 accum.
// Block 128x256, K-chunk 32, 4-stage cp.async pipeline, 8 warps (64x64 each).
// MODE 0: C -> bf16.  MODE 1: C -> fp32.  MODE 2: C -> fp32 + bias[n].
#define BM 128
#define BN 256
#define BK 32
#define STAGES 4
#define PITCH_B 80               // bytes per smem row (32 bf16 + 8 pad)
#define A_B   (BM*PITCH_B)       // 10240
#define B_B   (BN*PITCH_B)       // 20480
#define STAGE_B (A_B + B_B)      // 30720
#define GSMEM_BYTES (STAGES*STAGE_B)

template <int MODE>
__global__ void __launch_bounds__(256, 1) gemm_mma(
    const bf16* __restrict__ A, const bf16* __restrict__ B,
    float* __restrict__ Cf, bf16* __restrict__ Cb16,
    const float* __restrict__ bias,
    int K, int N, long long sA, long long sB, long long sC)
{
    extern __shared__ char smem[];
    const uint32_t smem0 = smem_u32(smem);

    const int tid = threadIdx.x;
    const int wid = tid >> 5;
    const int lane = tid & 31;
    const int m0 = blockIdx.y * BM;
    const int n0 = blockIdx.x * BN;
    const int warp_m = (wid & 1) * 64;
    const int warp_n = (wid >> 1) * 64;

    const bf16* pA = A + (size_t)blockIdx.z * sA;
    const bf16* pB = B + (size_t)blockIdx.z * sB;

    float acc[4][8][4];
#pragma unroll
    for (int a = 0; a < 4; a++)
#pragma unroll
        for (int b = 0; b < 8; b++)
#pragma unroll
            for (int c = 0; c < 4; c++) acc[a][b][c] = 0.0f;

    const int nch = K / BK;

    // -------- stage loader: A 128 rows + B 256 rows, 64B each = 6 cp16/thread
    auto load_stage = [&](int buf, int k0) {
        const uint32_t sb = smem0 + (uint32_t)buf * STAGE_B;
        // A: 512 cp16 tasks (128 rows x 4 segs)
        {
            const int task = tid * 2;
            const int row = task >> 2;
            const int seg = task & 3;
            const uint32_t off = (uint32_t)(row * PITCH_B + seg * 16);
            const bf16* src = pA + (size_t)(m0 + row) * K + k0 + seg * 8;
            cp16(sb + off,      src);
            cp16(sb + off + 16, src + 8);
        }
        // B: 1024 cp16 tasks (256 rows x 4 segs)
#pragma unroll
        for (int p = 0; p < 2; p++) {
            const int task = tid * 2 + p * 512;
            const int row = task >> 2;
            const int seg = task & 3;
            const uint32_t off = (uint32_t)(row * PITCH_B + seg * 16);
            const bf16* src = pB + (size_t)(n0 + row) * K + k0 + seg * 8;
            cp16(sb + A_B + off,      src);
            cp16(sb + A_B + off + 16, src + 8);
        }
    };

#pragma unroll
    for (int s = 0; s < STAGES - 1; s++) {
        if (s < nch) load_stage(s, s * BK);
        cp_commit();
    }

    const uint32_t a_off = (uint32_t)((lane & 15) * PITCH_B + ((lane >> 4) << 3) * 2);
    const uint32_t b_off = (uint32_t)(((((lane >> 4) << 3) + (lane & 7)) * PITCH_B)
                                      + (((lane >> 3) & 1) << 3) * 2);

    for (int ch = 0; ch < nch; ch++) {
        cp_wait<STAGES - 2>();
        __syncthreads();

        const int nxt = ch + STAGES - 1;
        if (nxt < nch) load_stage(nxt % STAGES, nxt * BK);
        cp_commit();

        const uint32_t sb = smem0 + (uint32_t)(ch % STAGES) * STAGE_B;
        const uint32_t sA_ = sb, sB_ = sb + A_B;

#pragma unroll
        for (int ks = 0; ks < 2; ks++) {
            const uint32_t kb = (uint32_t)(ks * 16 * 2);
            uint32_t ar[4][4];
#pragma unroll
            for (int mi = 0; mi < 4; mi++)
                ldsm4(ar[mi], sA_ + (uint32_t)((warp_m + mi * 16) * PITCH_B) + a_off + kb);
            uint32_t br[4][4];
#pragma unroll
            for (int nj = 0; nj < 4; nj++)
                ldsm4(br[nj], sB_ + (uint32_t)((warp_n + nj * 16) * PITCH_B) + b_off + kb);
#pragma unroll
            for (int mi = 0; mi < 4; mi++)
#pragma unroll
                for (int ni = 0; ni < 8; ni++)
                    mma16816(acc[mi][ni], ar[mi], &br[ni >> 1][(ni & 1) * 2]);
        }
    }
    cp_wait<0>();

    // -------- epilogue ------------------------------------------------------
#pragma unroll
    for (int mi = 0; mi < 4; mi++) {
#pragma unroll
        for (int ni = 0; ni < 8; ni++) {
            const int m = m0 + warp_m + mi * 16 + (lane >> 2);
            const int n = n0 + warp_n + ni * 8 + (lane & 3) * 2;
            float c0 = acc[mi][ni][0], c1 = acc[mi][ni][1];
            float c2 = acc[mi][ni][2], c3 = acc[mi][ni][3];
            if (MODE == 0) {
                __nv_bfloat162 h0 = __floats2bfloat162_rn(c0, c1);
                __nv_bfloat162 h1 = __floats2bfloat162_rn(c2, c3);
                *(uint32_t*)(Cb16 + (size_t)m * N + n)       = reinterpret_cast<uint32_t&>(h0);
                *(uint32_t*)(Cb16 + (size_t)(m + 8) * N + n) = reinterpret_cast<uint32_t&>(h1);
            } else {
                float* Cb = Cf + (size_t)blockIdx.z * sC;
                if (MODE == 2) {
                    float2 bv = *(const float2*)(bias + (size_t)blockIdx.z * CDIM + n);
                    c0 += bv.x; c1 += bv.y; c2 += bv.x; c3 += bv.y;
                }
                *(float2*)(Cb + (size_t)m * N + n)       = make_float2(c0, c1);
                *(float2*)(Cb + (size_t)(m + 8) * N + n) = make_float2(c2, c3);
            }
        }
    }
}

// ---------------- elementwise fp32 -> bf16 -----------------------------------
__global__ void __launch_bounds__(256) convert_hi(
    const float* __restrict__ x, bf16* __restrict__ h, size_t n)
{
    size_t i = ((size_t)blockIdx.x * 256 + threadIdx.x) * 8;
    if (i >= n) return;
    float4 a = *(const float4*)(x + i);
    float4 b = *(const float4*)(x + i + 4);
    __nv_bfloat162 h0 = __floats2bfloat162_rn(a.x, a.y);
    __nv_bfloat162 h1 = __floats2bfloat162_rn(a.z, a.w);
    __nv_bfloat162 h2 = __floats2bfloat162_rn(b.x, b.y);
    __nv_bfloat162 h3 = __floats2bfloat162_rn(b.z, b.w);
    *(uint4*)(h + i) = make_uint4(
        reinterpret_cast<uint32_t&>(h0), reinterpret_cast<uint32_t&>(h1),
        reinterpret_cast<uint32_t&>(h2), reinterpret_cast<uint32_t&>(h3));
}

// ---------------- V transpose: [B,N,C] -> [B,C,N] bf16 -----------------------
__global__ void __launch_bounds__(256) transpose_convert(
    const float* __restrict__ v, bf16* __restrict__ th)
{
    __shared__ float t[32][33];
    const float* vb = v + (size_t)blockIdx.z * SEQ * CDIM;
    const int c0 = blockIdx.x * 32, n0 = blockIdx.y * 32;
    for (int r = threadIdx.y; r < 32; r += 8)
        t[r][threadIdx.x] = vb[(size_t)(n0 + r) * CDIM + c0 + threadIdx.x];
    __syncthreads();
    bf16* thb = th + (size_t)blockIdx.z * CDIM * SEQ;
    for (int r = threadIdx.y; r < 32; r += 8) {
        size_t o = (size_t)(c0 + r) * SEQ + n0 + threadIdx.x;
        thb[o] = __float2bfloat16(t[threadIdx.x][r]);
    }
}

// ---------------- column mean of V: bias[b][c] = mean_n v[b][n][c] ----------
__global__ void __launch_bounds__(256) colmean_v(
    const float* __restrict__ v, float* __restrict__ bias)
{
    const int b = blockIdx.y;
    const int c = blockIdx.x * 256 + threadIdx.x;
    const float* vb = v + (size_t)b * SEQ * CDIM + c;
    float s0 = 0.f, s1 = 0.f, s2 = 0.f, s3 = 0.f;
#pragma unroll 4
    for (int i = 0; i < SEQ; i += 4) {
        s0 += vb[(size_t)(i + 0) * CDIM];
        s1 += vb[(size_t)(i + 1) * CDIM];
        s2 += vb[(size_t)(i + 2) * CDIM];
        s3 += vb[(size_t)(i + 3) * CDIM];
    }
    bias[(size_t)b * CDIM + c] = (s0 + s1 + s2 + s3) * (1.0f / SEQ);
}

// ---------------- softmax: S fp32 -> dP = softmax - 1/SEQ (bf16) ------------
__global__ void __launch_bounds__(256) softmax_kernel(
    const float* __restrict__ S, bf16* __restrict__ Dp, float scale)
{
    const float* row = S + (size_t)blockIdx.x * SEQ;
    bf16* dp = Dp + (size_t)blockIdx.x * SEQ;
    const int tid = threadIdx.x;

    float vals[8];
    float mx = -1e30f;
#pragma unroll
    for (int i = 0; i < 8; i++) {
        vals[i] = row[tid + i * 256] * scale;
        mx = fmaxf(mx, vals[i]);
    }
    __shared__ float red[256];
    red[tid] = mx; __syncthreads();
    for (int s = 128; s > 0; s >>= 1) {
        if (tid < s) red[tid] = fmaxf(red[tid], red[tid + s]);
        __syncthreads();
    }
    mx = red[0]; __syncthreads();
    float sum = 0.0f;
#pragma unroll
    for (int i = 0; i < 8; i++) { vals[i] = __expf(vals[i] - mx); sum += vals[i]; }
    red[tid] = sum; __syncthreads();
    for (int s = 128; s > 0; s >>= 1) {
        if (tid < s) red[tid] += red[tid + s];
        __syncthreads();
    }
    const float inv = 1.0f / red[0];
    const float u = 1.0f / (float)SEQ;
#pragma unroll
    for (int i = 0; i < 8; i++)
        dp[tid + i * 256] = __float2bfloat16(vals[i] * inv - u);
}

// ---------------- launch -----------------------------------------------------
extern "C" void kernel_launch(void* const* d_in, const int* in_sizes, int n_in,
                              void* d_out, int out_size)
{
    const float* q_x = (const float*)d_in[0];
    const float* k_x = (const float*)d_in[1];
    const float* v_x = (const float*)d_in[2];
    const float* Wq  = (const float*)d_in[3];
    const float* Wk  = (const float*)d_in[4];
    float* out = (float*)d_out;

    bf16 *qx, *kx, *w, *q, *k, *vt, *dp;
    float *s, *bias;
    cudaGetSymbolAddress((void**)&qx, g_qx);
    cudaGetSymbolAddress((void**)&kx, g_kx);
    cudaGetSymbolAddress((void**)&w,  g_w);
    cudaGetSymbolAddress((void**)&q,  g_q);
    cudaGetSymbolAddress((void**)&k,  g_k);
    cudaGetSymbolAddress((void**)&vt, g_vt);
    cudaGetSymbolAddress((void**)&s,  g_s);
    cudaGetSymbolAddress((void**)&dp, g_dp);
    cudaGetSymbolAddress((void**)&bias, g_bias);

    cudaFuncSetAttribute(gemm_mma<0>, cudaFuncAttributeMaxDynamicSharedMemorySize, GSMEM_BYTES);
    cudaFuncSetAttribute(gemm_mma<1>, cudaFuncAttributeMaxDynamicSharedMemorySize, GSMEM_BYTES);
    cudaFuncSetAttribute(gemm_mma<2>, cudaFuncAttributeMaxDynamicSharedMemorySize, GSMEM_BYTES);

    const size_t nx = (size_t)MQ * CDIM;
    const size_t nw = (size_t)KD * CDIM;

    // 1) converts + V transpose + V column mean
    convert_hi<<<(unsigned)(nx / 8 / 256), 256>>>(q_x, qx, nx);
    convert_hi<<<(unsigned)(nx / 8 / 256), 256>>>(k_x, kx, nx);
    convert_hi<<<(unsigned)(nw / 8 / 256), 256>>>(Wq, w, nw);
    convert_hi<<<(unsigned)(nw / 8 / 256), 256>>>(Wk, w + nw, nw);
    transpose_convert<<<dim3(CDIM / 32, SEQ / 32, BATCH), dim3(32, 8)>>>(v_x, vt);
    colmean_v<<<dim3(CDIM / 256, BATCH), 256>>>(v_x, bias);

    // 2) projections: Q = qx @ Wq^T, K = kx @ Wk^T (bf16 out)
    gemm_mma<0><<<dim3(KD / BN, MQ / BM, 1), 256, GSMEM_BYTES>>>(
        qx, w, nullptr, q, nullptr, CDIM, KD, 0, 0, 0);
    gemm_mma<0><<<dim3(KD / BN, MQ / BM, 1), 256, GSMEM_BYTES>>>(
        kx, w + nw, nullptr, k, nullptr, CDIM, KD, 0, 0, 0);

    // 3) S = Q @ K^T per batch (fp32)
    gemm_mma<1><<<dim3(SEQ / BN, SEQ / BM, BATCH), 256, GSMEM_BYTES>>>(
        q, k, s, nullptr, nullptr, KD, SEQ,
        (long long)SEQ * KD, (long long)SEQ * KD, (long long)SEQ * SEQ);

    // 4) dP = softmax(S/768) - 1/SEQ  (bf16)
    softmax_kernel<<<MQ, 256>>>(s, dp, 1.0f / (float)KD);

    // 5) out = dP @ Vt^T + colmean(V)  per batch (fp32)
    gemm_mma<2><<<dim3(CDIM / BN, SEQ / BM, BATCH), 256, GSMEM_BYTES>>>(
        dp, vt, out, nullptr, bias, SEQ, CDIM,
        (long long)SEQ * SEQ, (long long)CDIM * SEQ, (long long)SEQ * CDIM);
}

// round 10
// speedup vs baseline: 1.2612x; 1.2612x over previous
#include <cuda_runtime.h>
#include <cuda_bf16.h>
#include <cstdint>

#define BATCH 8
#define SEQ   2048
#define CDIM  768
#define KD    768
#define MQ    (BATCH*SEQ)

typedef __nv_bfloat16 bf16;

// ---------------- scratch (device globals; allocation-free rule) -------------
__device__ bf16  g_qx[(size_t)MQ*CDIM];              // qx bf16
__device__ bf16  g_kx[(size_t)MQ*CDIM];              // kx bf16
__device__ bf16  g_wt[(size_t)2*KD*CDIM];            // WqT, WkT bf16
__device__ bf16  g_mt[(size_t)KD*CDIM];              // MT[c'][c] = M[c][c']
__device__ bf16  g_qp[(size_t)MQ*KD];                // q' = qx @ M
__device__ bf16  g_e [(size_t)BATCH*SEQ*SEQ];        // E' = exp(S*scale)-1
__device__ bf16  g_vt[(size_t)BATCH*CDIM*SEQ];       // V^T bf16
__device__ float g_colsum[(size_t)BATCH*CDIM];       // colsum of V (fp32 exact)
__device__ float g_inv  [(size_t)MQ];                // 1/(SEQ + rowsum(E'))

// ---------------- helpers ----------------------------------------------------
__device__ __forceinline__ uint32_t smem_u32(const void* p) {
    uint32_t a;
    asm("{ .reg .u64 t; cvta.to.shared.u64 t, %1; cvt.u32.u64 %0, t; }" : "=r"(a) : "l"(p));
    return a;
}
__device__ __forceinline__ void cp16(uint32_t dst, const void* src) {
    asm volatile("cp.async.cg.shared.global [%0], [%1], 16;" :: "r"(dst), "l"(src));
}
__device__ __forceinline__ void cp_commit() {
    asm volatile("cp.async.commit_group;" ::: "memory");
}
template <int N>
__device__ __forceinline__ void cp_wait() {
    asm volatile("cp.async.wait_group %0;" :: "n"(N) : "memory");
}
__device__ __forceinline__ void ldsm4(uint32_t* r, uint32_t addr) {
    asm volatile("ldmatrix.sync.aligned.m8n8.x4.shared.b16 {%0,%1,%2,%3}, [%4];"
                 : "=r"(r[0]), "=r"(r[1]), "=r"(r[2]), "=r"(r[3]) : "r"(addr));
}
__device__ __forceinline__ void mma16816(float* c, const uint32_t* a, const uint32_t* b) {
    asm volatile(
        "mma.sync.aligned.m16n8k16.row.col.f32.bf16.bf16.f32 "
        "{%0,%1,%2,%3}, {%4,%5,%6,%7}, {%8,%9}, {%0,%1,%2,%3};"
        : "+f"(c[0]), "+f"(c[1]), "+f"(c[2]), "+f"(c[3])
        : "r"(a[0]), "r"(a[1]), "r"(a[2]), "r"(a[3]), "r"(b[0]), "r"(b[1]));
}

// ---------------- single-bf16 NT GEMM via mma.sync (R7 core) -----------------
// C[m,n] = sum_k A[m,k]*B[n,k]; A,B bf16, K-major, fp32 accum.
// Block 128x128, K-chunk 32, 4-stage cp.async pipeline, 8 warps (64x32 each).
// MODE 0: C -> bf16 plain.
// MODE 3: C -> bf16 of (exp(c*scale)-1).
// MODE 4: C -> fp32 of (c + colsum[n]) * inv_denom[m].
#define BM 128
#define BN 128
#define BK 32
#define STAGES 4
#define PITCH_B 80               // bytes per smem row (32 bf16 + 8 pad)
#define MAT_B  (128*PITCH_B)     // 10240 bytes per matrix tile
#define STAGE_B (2*MAT_B)
#define GSMEM_BYTES (STAGES*STAGE_B)

template <int MODE>
__global__ void __launch_bounds__(256) gemm_mma(
    const bf16* __restrict__ A, const bf16* __restrict__ B,
    float* __restrict__ Cf, bf16* __restrict__ Cb16,
    const float* __restrict__ bias, const float* __restrict__ denom, float scale,
    int K, int N, long long sA, long long sB, long long sC)
{
    extern __shared__ char smem[];
    const uint32_t smem0 = smem_u32(smem);

    const int tid = threadIdx.x;
    const int wid = tid >> 5;
    const int lane = tid & 31;
    const int m0 = blockIdx.y * BM;
    const int n0 = blockIdx.x * BN;
    const int warp_m = (wid & 1) * 64;
    const int warp_n = (wid >> 1) * 32;

    const bf16* pA = A + (size_t)blockIdx.z * sA;
    const bf16* pB = B + (size_t)blockIdx.z * sB;

    float acc[4][4][4];
#pragma unroll
    for (int a = 0; a < 4; a++)
#pragma unroll
        for (int b = 0; b < 4; b++)
#pragma unroll
            for (int c = 0; c < 4; c++) acc[a][b][c] = 0.0f;

    const int nch = K / BK;

    auto load_stage = [&](int buf, int k0) {
        const uint32_t sb = smem0 + (uint32_t)buf * STAGE_B;
#pragma unroll
        for (int p = 0; p < 2; p++) {
            const int task = tid + p * 256;
            const int row = task >> 2;
            const int seg = task & 3;
            const uint32_t off = (uint32_t)(row * PITCH_B + seg * 16);
            const int ge = k0 + seg * 8;
            cp16(sb +         off, pA + (size_t)(m0 + row) * K + ge);
            cp16(sb + MAT_B + off, pB + (size_t)(n0 + row) * K + ge);
        }
    };

#pragma unroll
    for (int s = 0; s < STAGES - 1; s++) {
        if (s < nch) load_stage(s, s * BK);
        cp_commit();
    }

    const uint32_t a_off = (uint32_t)((lane & 15) * PITCH_B + ((lane >> 4) << 3) * 2);
    const uint32_t b_off = (uint32_t)(((((lane >> 4) << 3) + (lane & 7)) * PITCH_B)
                                      + (((lane >> 3) & 1) << 3) * 2);

    for (int ch = 0; ch < nch; ch++) {
        cp_wait<STAGES - 2>();
        __syncthreads();

        const int nxt = ch + STAGES - 1;
        if (nxt < nch) load_stage(nxt % STAGES, nxt * BK);
        cp_commit();

        const uint32_t sb = smem0 + (uint32_t)(ch % STAGES) * STAGE_B;
        const uint32_t sA_ = sb, sB_ = sb + MAT_B;

#pragma unroll
        for (int ks = 0; ks < 2; ks++) {
            const uint32_t kb = (uint32_t)(ks * 16 * 2);
            uint32_t ar[4][4];
#pragma unroll
            for (int mi = 0; mi < 4; mi++)
                ldsm4(ar[mi], sA_ + (uint32_t)((warp_m + mi * 16) * PITCH_B) + a_off + kb);
            uint32_t br[2][4];
#pragma unroll
            for (int nj = 0; nj < 2; nj++)
                ldsm4(br[nj], sB_ + (uint32_t)((warp_n + nj * 16) * PITCH_B) + b_off + kb);
#pragma unroll
            for (int mi = 0; mi < 4; mi++)
#pragma unroll
                for (int ni = 0; ni < 4; ni++)
                    mma16816(acc[mi][ni], ar[mi], &br[ni >> 1][(ni & 1) * 2]);
        }
    }
    cp_wait<0>();

    // -------- epilogue ------------------------------------------------------
#pragma unroll
    for (int mi = 0; mi < 4; mi++) {
#pragma unroll
        for (int ni = 0; ni < 4; ni++) {
            const int m = m0 + warp_m + mi * 16 + (lane >> 2);
            const int n = n0 + warp_n + ni * 8 + (lane & 3) * 2;
            float c0 = acc[mi][ni][0], c1 = acc[mi][ni][1];
            float c2 = acc[mi][ni][2], c3 = acc[mi][ni][3];
            if (MODE == 0 || MODE == 3) {
                if (MODE == 3) {
                    c0 = __expf(c0 * scale) - 1.0f;
                    c1 = __expf(c1 * scale) - 1.0f;
                    c2 = __expf(c2 * scale) - 1.0f;
                    c3 = __expf(c3 * scale) - 1.0f;
                }
                bf16* Cz = Cb16 + (size_t)blockIdx.z * sC;
                __nv_bfloat162 h0 = __floats2bfloat162_rn(c0, c1);
                __nv_bfloat162 h1 = __floats2bfloat162_rn(c2, c3);
                *(uint32_t*)(Cz + (size_t)m * N + n)       = reinterpret_cast<uint32_t&>(h0);
                *(uint32_t*)(Cz + (size_t)(m + 8) * N + n) = reinterpret_cast<uint32_t&>(h1);
            } else {  // MODE 4
                float* Cb = Cf + (size_t)blockIdx.z * sC;
                float2 bv = *(const float2*)(bias + (size_t)blockIdx.z * CDIM + n);
                float i0 = denom[(size_t)blockIdx.z * SEQ + m];
                float i1 = denom[(size_t)blockIdx.z * SEQ + m + 8];
                *(float2*)(Cb + (size_t)m * N + n) =
                    make_float2((c0 + bv.x) * i0, (c1 + bv.y) * i0);
                *(float2*)(Cb + (size_t)(m + 8) * N + n) =
                    make_float2((c2 + bv.x) * i1, (c3 + bv.y) * i1);
            }
        }
    }
}

// ---------------- elementwise fp32 -> bf16 -----------------------------------
__global__ void __launch_bounds__(256) convert_hi(
    const float* __restrict__ x, bf16* __restrict__ h, size_t n)
{
    size_t i = ((size_t)blockIdx.x * 256 + threadIdx.x) * 8;
    if (i >= n) return;
    float4 a = *(const float4*)(x + i);
    float4 b = *(const float4*)(x + i + 4);
    __nv_bfloat162 h0 = __floats2bfloat162_rn(a.x, a.y);
    __nv_bfloat162 h1 = __floats2bfloat162_rn(a.z, a.w);
    __nv_bfloat162 h2 = __floats2bfloat162_rn(b.x, b.y);
    __nv_bfloat162 h3 = __floats2bfloat162_rn(b.z, b.w);
    *(uint4*)(h + i) = make_uint4(
        reinterpret_cast<uint32_t&>(h0), reinterpret_cast<uint32_t&>(h1),
        reinterpret_cast<uint32_t&>(h2), reinterpret_cast<uint32_t&>(h3));
}

// ---------------- generic transpose: [R,C] fp32 -> [C,R] bf16 ----------------
__global__ void __launch_bounds__(256) transpose_convert(
    const float* __restrict__ in, bf16* __restrict__ out,
    int R, int C, long long sIn, long long sOut)
{
    __shared__ float t[32][33];
    const float* ib = in + (size_t)blockIdx.z * sIn;
    bf16* ob = out + (size_t)blockIdx.z * sOut;
    const int c0 = blockIdx.x * 32, r0 = blockIdx.y * 32;
    for (int r = threadIdx.y; r < 32; r += 8)
        t[r][threadIdx.x] = ib[(size_t)(r0 + r) * C + c0 + threadIdx.x];
    __syncthreads();
    for (int r = threadIdx.y; r < 32; r += 8)
        ob[(size_t)(c0 + r) * R + r0 + threadIdx.x] = __float2bfloat16(t[threadIdx.x][r]);
}

// ---------------- column sum of V: colsum[b][c] = sum_n v[b][n][c] ----------
__global__ void __launch_bounds__(256) colsum_v(
    const float* __restrict__ v, float* __restrict__ cs)
{
    const int b = blockIdx.y;
    const int c = blockIdx.x * 256 + threadIdx.x;
    const float* vb = v + (size_t)b * SEQ * CDIM + c;
    float s0 = 0.f, s1 = 0.f, s2 = 0.f, s3 = 0.f;
#pragma unroll 4
    for (int i = 0; i < SEQ; i += 4) {
        s0 += vb[(size_t)(i + 0) * CDIM];
        s1 += vb[(size_t)(i + 1) * CDIM];
        s2 += vb[(size_t)(i + 2) * CDIM];
        s3 += vb[(size_t)(i + 3) * CDIM];
    }
    cs[(size_t)b * CDIM + c] = s0 + s1 + s2 + s3;
}

// ---------------- row sum of E' -> inv_denom = 1/(SEQ + rowsum) -------------
__global__ void __launch_bounds__(256) rowsum_exp(
    const bf16* __restrict__ E, float* __restrict__ inv)
{
    const bf16* row = E + (size_t)blockIdx.x * SEQ;
    const int tid = threadIdx.x;
    uint4 v = *(const uint4*)(row + tid * 8);
    const __nv_bfloat162* p = reinterpret_cast<const __nv_bfloat162*>(&v);
    float s = 0.f;
#pragma unroll
    for (int j = 0; j < 4; j++) {
        float2 f = __bfloat1622float2(p[j]);
        s += f.x + f.y;
    }
    __shared__ float red[256];
    red[tid] = s; __syncthreads();
    for (int st = 128; st > 0; st >>= 1) {
        if (tid < st) red[tid] += red[tid + st];
        __syncthreads();
    }
    if (tid == 0) inv[blockIdx.x] = 1.0f / ((float)SEQ + red[0]);
}

// ---------------- launch -----------------------------------------------------
extern "C" void kernel_launch(void* const* d_in, const int* in_sizes, int n_in,
                              void* d_out, int out_size)
{
    const float* q_x = (const float*)d_in[0];
    const float* k_x = (const float*)d_in[1];
    const float* v_x = (const float*)d_in[2];
    const float* Wq  = (const float*)d_in[3];
    const float* Wk  = (const float*)d_in[4];
    float* out = (float*)d_out;

    bf16 *qx, *kx, *wt, *mt, *qp, *e, *vt;
    float *colsum, *inv;
    cudaGetSymbolAddress((void**)&qx, g_qx);
    cudaGetSymbolAddress((void**)&kx, g_kx);
    cudaGetSymbolAddress((void**)&wt, g_wt);
    cudaGetSymbolAddress((void**)&mt, g_mt);
    cudaGetSymbolAddress((void**)&qp, g_qp);
    cudaGetSymbolAddress((void**)&e,  g_e);
    cudaGetSymbolAddress((void**)&vt, g_vt);
    cudaGetSymbolAddress((void**)&colsum, g_colsum);
    cudaGetSymbolAddress((void**)&inv, g_inv);

    cudaFuncSetAttribute(gemm_mma<0>, cudaFuncAttributeMaxDynamicSharedMemorySize, GSMEM_BYTES);
    cudaFuncSetAttribute(gemm_mma<3>, cudaFuncAttributeMaxDynamicSharedMemorySize, GSMEM_BYTES);
    cudaFuncSetAttribute(gemm_mma<4>, cudaFuncAttributeMaxDynamicSharedMemorySize, GSMEM_BYTES);

    const size_t nx = (size_t)MQ * CDIM;
    const size_t nw = (size_t)KD * CDIM;

    // 1) converts / transposes / V colsum
    convert_hi<<<(unsigned)(nx / 8 / 256), 256>>>(q_x, qx, nx);
    convert_hi<<<(unsigned)(nx / 8 / 256), 256>>>(k_x, kx, nx);
    transpose_convert<<<dim3(CDIM / 32, KD / 32, 1), dim3(32, 8)>>>(
        Wq, wt, KD, CDIM, 0, 0);                         // WqT [c][d]
    transpose_convert<<<dim3(CDIM / 32, KD / 32, 1), dim3(32, 8)>>>(
        Wk, wt + nw, KD, CDIM, 0, 0);                    // WkT [c'][d]
    transpose_convert<<<dim3(CDIM / 32, SEQ / 32, BATCH), dim3(32, 8)>>>(
        v_x, vt, SEQ, CDIM, (long long)SEQ * CDIM, (long long)CDIM * SEQ);
    colsum_v<<<dim3(CDIM / 256, BATCH), 256>>>(v_x, colsum);

    // 2) MT[c'][c] = sum_d WkT[c'][d] * WqT[c][d]  (= M[c][c'])
    gemm_mma<0><<<dim3(CDIM / BN, KD / BM, 1), 256, GSMEM_BYTES>>>(
        wt + nw, wt, nullptr, mt, nullptr, nullptr, 0.f, KD, CDIM, 0, 0, 0);

    // 3) q'[m][c'] = sum_c qx[m][c] * MT[c'][c]
    gemm_mma<0><<<dim3(KD / BN, MQ / BM, 1), 256, GSMEM_BYTES>>>(
        qx, mt, nullptr, qp, nullptr, nullptr, 0.f, CDIM, KD, 0, 0, 0);

    // 4) E' = exp((q' @ kx^T) * scale) - 1  per batch (bf16)
    gemm_mma<3><<<dim3(SEQ / BN, SEQ / BM, BATCH), 256, GSMEM_BYTES>>>(
        qp, kx, nullptr, e, nullptr, nullptr, 1.0f / (float)KD, KD, SEQ,
        (long long)SEQ * KD, (long long)SEQ * CDIM, (long long)SEQ * SEQ);

    // 5) inv_denom[m] = 1 / (SEQ + rowsum(E'))
    rowsum_exp<<<MQ, 256>>>(e, inv);

    // 6) out = (E' @ Vt^T + colsum) * inv_denom  per batch (fp32)
    gemm_mma<4><<<dim3(CDIM / BN, SEQ / BM, BATCH), 256, GSMEM_BYTES>>>(
        e, vt, out, nullptr, colsum, inv, 0.f, SEQ, CDIM,
        (long long)SEQ * SEQ, (long long)CDIM * SEQ, (long long)SEQ * CDIM);
}